// round 16
// baseline (speedup 1.0000x reference)
#include <cuda_runtime.h>

#define MAXN 500000
#define SLOT 64
#define STEP_DIM 8
#define NGRP ((MAXN + 31) / 32)
#define NBLOCKS 1184          // 148 SMs x 8 blocks; forced resident via launch_bounds

// Interleaved bucketed CSR:
// slot p of node i lives at g_csr[(i>>5)*(32*SLOT) + p*32 + (i&31)]
__device__ int    g_cnt[MAXN];
__device__ int    g_csr[NGRP * 32 * SLOT + 32 * 8];
__device__ float  g_dis[MAXN];
__device__ float2 g_zpA[MAXN];
__device__ float2 g_zpB[MAXN];
__device__ float2 g_acc[MAXN];
__device__ int    g_bar_cnt;   // software grid barrier counter (reset each call)

__device__ __forceinline__ int slot_addr(int node, int p) {
    return (node >> 5) * (32 * SLOT) + (p << 5) + (node & 31);
}

// ---------------------------------------------------------------------------
__global__ void k_reset(int n) {
    int i = blockIdx.x * blockDim.x + threadIdx.x;
    if (i < n) g_cnt[i] = 0;
    if (i == 0) g_bar_cnt = 0;
}

// Single-pass bucketed fill. Edge arrays read-once -> streaming loads.
__global__ void k_fill(const int* __restrict__ src, const int* __restrict__ dst, int e) {
    int base = (blockIdx.x * blockDim.x + threadIdx.x) * 4;
    if (base + 3 < e) {
        int4 s4 = __ldcs(reinterpret_cast<const int4*>(src + base));
        int4 d4 = __ldcs(reinterpret_cast<const int4*>(dst + base));
        int p;
        p = atomicAdd(&g_cnt[d4.x], 1); if (p < SLOT) g_csr[slot_addr(d4.x, p)] = s4.x;
        p = atomicAdd(&g_cnt[d4.y], 1); if (p < SLOT) g_csr[slot_addr(d4.y, p)] = s4.y;
        p = atomicAdd(&g_cnt[d4.z], 1); if (p < SLOT) g_csr[slot_addr(d4.z, p)] = s4.z;
        p = atomicAdd(&g_cnt[d4.w], 1); if (p < SLOT) g_csr[slot_addr(d4.w, p)] = s4.w;
    } else {
        for (int i = base; i < e; i++) {
            int d = dst[i];
            int p = atomicAdd(&g_cnt[d], 1);
            if (p < SLOT) g_csr[slot_addr(d, p)] = src[i];
        }
    }
}

// ---------------------------------------------------------------------------
// Layer-0 node kernel: deg = cnt+1 (self-loop); dis = rsqrt(deg)
__global__ void k_node0(const float* __restrict__ X,
                        const int*   __restrict__ step_index,
                        const float* __restrict__ step_emb,
                        const float* __restrict__ W0,   // [2][10][2]
                        const float* __restrict__ b0,   // [2][2]
                        int n) {
    int i = blockIdx.x * blockDim.x + threadIdx.x;
    if (i >= n) return;
    float dis = rsqrtf((float)(g_cnt[i] + 1));
    g_dis[i] = dis;

    float2 x = *reinterpret_cast<const float2*>(X + 2 * i);
    const float* s = step_emb + (*step_index) * STEP_DIM;

    float a0 = x.x * W0[0]      + x.y * W0[2];
    float a1 = x.x * W0[1]      + x.y * W0[3];
    float z0 = x.x * W0[20 + 0] + x.y * W0[20 + 2];
    float z1 = x.x * W0[20 + 1] + x.y * W0[20 + 3];
#pragma unroll
    for (int j = 0; j < STEP_DIM; j++) {
        float sv = s[j];
        a0 += sv * W0[(2 + j) * 2 + 0];
        a1 += sv * W0[(2 + j) * 2 + 1];
        z0 += sv * W0[20 + (2 + j) * 2 + 0];
        z1 += sv * W0[20 + (2 + j) * 2 + 1];
    }
    a0 += b0[0] + b0[2];
    a1 += b0[1] + b0[3];

    float d2 = dis * dis;
    g_zpA[i] = make_float2(z0 * dis, z1 * dis);
    g_acc[i] = make_float2(a0 + z0 * d2, a1 + z1 * d2);
}

// ---------------------------------------------------------------------------
// Software grid barrier (threadFenceReduction pattern). All NBLOCKS blocks are
// resident (launch_bounds-forced occupancy), so spinning is deadlock-free.
__device__ __forceinline__ void grid_bar(int target) {
    __threadfence();
    __syncthreads();
    if (threadIdx.x == 0) {
        atomicAdd(&g_bar_cnt, 1);
        while (*(volatile int*)&g_bar_cnt < target) __nanosleep(64);
    }
    __syncthreads();
}

// Half-row pull. CSR/cnt are immutable during the persistent kernel -> L1 ok
// (__ldg). zp is written by OTHER SMs between phases -> must bypass L1 (__ldcg).
__device__ __forceinline__ float2 pull_half(const float2* zin, int i, int deg, int half) {
    const int* base = g_csr + (i >> 5) * (32 * SLOT) + (i & 31);
    float sx = 0.f, sy = 0.f;
    for (int j = half * 8; j < deg; j += 16) {
        int ids[8];
#pragma unroll
        for (int k = 0; k < 8; k++)
            ids[k] = __ldg(base + ((j + k) << 5));
#pragma unroll
        for (int k = 0; k < 8; k++) {
            if (j + k < deg) {
                float2 z = __ldcg(const_cast<float2*>(zin) + ids[k]);
                sx += z.x; sy += z.y;
            }
        }
    }
    return make_float2(sx, sy);
}

// Persistent fused kernel: layers 1..7 + final, grid barrier between phases.
__global__ void __launch_bounds__(256, 8)
k_fused(const float* __restrict__ Wh,   // [7][2][2][2]
        const float* __restrict__ bh,   // [7][2][2]
        float2* __restrict__ out, int n) {
    int stride = gridDim.x * blockDim.x;
    int gtid = blockIdx.x * blockDim.x + threadIdx.x;
    int n2 = 2 * n;

    for (int l = 1; l <= 8; l++) {
        const float2* zin  = (l & 1) ? g_zpA : g_zpB;
        float2*       zout = (l & 1) ? g_zpB : g_zpA;
        bool fin = (l == 8);
        const float* W = Wh + (l - 1) * 8;   // not dereferenced when fin
        const float* b = bh + (l - 1) * 4;

        for (int t = gtid; t < n2; t += stride) {
            int i = t >> 1;
            int half = t & 1;
            int deg = min(__ldg(&g_cnt[i]), SLOT);
            float2 s = pull_half(zin, i, deg, half);

            unsigned mask = __activemask();   // pairs are co-active (n2 even, stride even)
            s.x += __shfl_xor_sync(mask, s.x, 1);
            s.y += __shfl_xor_sync(mask, s.y, 1);
            if (half) continue;

            float  dis = g_dis[i];
            float2 acc = g_acc[i];
            float x0 = fmaxf(acc.x + dis * s.x, 0.f);
            float x1 = fmaxf(acc.y + dis * s.y, 0.f);

            if (fin) {
                out[i] = make_float2(x0, x1);
            } else {
                float a0 = x0 * W[0] + x1 * W[2] + b[0] + b[2];
                float a1 = x0 * W[1] + x1 * W[3] + b[1] + b[3];
                float z0 = x0 * W[4] + x1 * W[6];
                float z1 = x0 * W[5] + x1 * W[7];
                float d2 = dis * dis;
                zout[i]  = make_float2(z0 * dis, z1 * dis);
                g_acc[i] = make_float2(a0 + z0 * d2, a1 + z1 * d2);
            }
        }
        if (!fin) grid_bar(l * NBLOCKS);
    }
}

// ---------------------------------------------------------------------------
extern "C" void kernel_launch(void* const* d_in, const int* in_sizes, int n_in,
                              void* d_out, int out_size) {
    const float* X          = (const float*)d_in[0];
    const int*   edge_index = (const int*)  d_in[1];
    const int*   step_index = (const int*)  d_in[2];
    const float* step_emb   = (const float*)d_in[3];
    const float* W0         = (const float*)d_in[4];
    const float* b0         = (const float*)d_in[5];
    const float* Wh         = (const float*)d_in[6];
    const float* bh         = (const float*)d_in[7];

    int n = in_sizes[0] / 2;        // C = 2
    int e = in_sizes[1] / 2;        // edge_index is [2, E]
    const int* src = edge_index;
    const int* dst = edge_index + e;

    const int T = 256;
    int nb_node = (n + T - 1) / T;
    int nb_edge = ((e + 3) / 4 + T - 1) / T;

    k_reset<<<nb_node, T>>>(n);
    k_fill<<<nb_edge, T>>>(src, dst, e);
    k_node0<<<nb_node, T>>>(X, step_index, step_emb, W0, b0, n);
    k_fused<<<NBLOCKS, T>>>(Wh, bh, (float2*)d_out, n);
}

// round 17
// speedup vs baseline: 1.1617x; 1.1617x over previous
#include <cuda_runtime.h>

#define MAXN 500000
#define SLOT 64
#define STEP_DIM 8
#define NGRP ((MAXN + 31) / 32)

// Interleaved bucketed CSR:
// slot p of node i lives at g_csr[(i>>5)*(32*SLOT) + p*32 + (i&31)]
// Padded by 8 slots for the unconditional batched reader (over-read slots
// always contain valid node ids: other rows / zero-init; gathers predicated).
__device__ int    g_cnt[MAXN];
__device__ int    g_csr[NGRP * 32 * SLOT + 32 * 8];
__device__ float  g_dis[MAXN];
__device__ float2 g_zpA[MAXN];
__device__ float2 g_zpB[MAXN];
__device__ float2 g_acc[MAXN];

__device__ __forceinline__ int slot_addr(int node, int p) {
    return (node >> 5) * (32 * SLOT) + (p << 5) + (node & 31);
}

// ---------------------------------------------------------------------------
__global__ void k_reset(int n) {
    int i = blockIdx.x * blockDim.x + threadIdx.x;
    if (i < n) g_cnt[i] = 0;
}

// Single-pass bucketed fill. Edge arrays read-once -> streaming loads.
__global__ void k_fill(const int* __restrict__ src, const int* __restrict__ dst, int e) {
    int base = (blockIdx.x * blockDim.x + threadIdx.x) * 4;
    if (base + 3 < e) {
        int4 s4 = __ldcs(reinterpret_cast<const int4*>(src + base));
        int4 d4 = __ldcs(reinterpret_cast<const int4*>(dst + base));
        int p;
        p = atomicAdd(&g_cnt[d4.x], 1); if (p < SLOT) g_csr[slot_addr(d4.x, p)] = s4.x;
        p = atomicAdd(&g_cnt[d4.y], 1); if (p < SLOT) g_csr[slot_addr(d4.y, p)] = s4.y;
        p = atomicAdd(&g_cnt[d4.z], 1); if (p < SLOT) g_csr[slot_addr(d4.z, p)] = s4.z;
        p = atomicAdd(&g_cnt[d4.w], 1); if (p < SLOT) g_csr[slot_addr(d4.w, p)] = s4.w;
    } else {
        for (int i = base; i < e; i++) {
            int d = dst[i];
            int p = atomicAdd(&g_cnt[d], 1);
            if (p < SLOT) g_csr[slot_addr(d, p)] = src[i];
        }
    }
}

// ---------------------------------------------------------------------------
// Layer-0 node kernel: deg = cnt+1 (self-loop); dis = rsqrt(deg)
__global__ void k_node0(const float* __restrict__ X,
                        const int*   __restrict__ step_index,
                        const float* __restrict__ step_emb,
                        const float* __restrict__ W0,   // [2][10][2]
                        const float* __restrict__ b0,   // [2][2]
                        int n) {
    int i = blockIdx.x * blockDim.x + threadIdx.x;
    if (i >= n) return;
    float dis = rsqrtf((float)(g_cnt[i] + 1));
    g_dis[i] = dis;

    float2 x = *reinterpret_cast<const float2*>(X + 2 * i);
    const float* s = step_emb + (*step_index) * STEP_DIM;

    float a0 = x.x * W0[0]      + x.y * W0[2];
    float a1 = x.x * W0[1]      + x.y * W0[3];
    float z0 = x.x * W0[20 + 0] + x.y * W0[20 + 2];
    float z1 = x.x * W0[20 + 1] + x.y * W0[20 + 3];
#pragma unroll
    for (int j = 0; j < STEP_DIM; j++) {
        float sv = s[j];
        a0 += sv * W0[(2 + j) * 2 + 0];
        a1 += sv * W0[(2 + j) * 2 + 1];
        z0 += sv * W0[20 + (2 + j) * 2 + 0];
        z1 += sv * W0[20 + (2 + j) * 2 + 1];
    }
    a0 += b0[0] + b0[2];
    a1 += b0[1] + b0[3];

    float d2 = dis * dis;
    g_zpA[i] = make_float2(z0 * dis, z1 * dis);
    g_acc[i] = make_float2(a0 + z0 * d2, a1 + z1 * d2);
}

// ---------------------------------------------------------------------------
// Chain-shortened half-row pull:
// The first batch's 8 id loads are issued UNCONDITIONALLY (addresses don't
// depend on deg; slots half*8..half*8+7 <= 15 < SLOT are always in bounds),
// concurrent with the caller's cnt load. Gathers are predicated on deg.
// Only deg > 16 continues into the loop (by then deg is known).
__device__ __forceinline__ float2 pull_half(const float2* __restrict__ zin,
                                            const int* base, int deg, int half) {
    int j0 = half * 8;
    int ids[8];
#pragma unroll
    for (int k = 0; k < 8; k++)
        ids[k] = __ldg(base + ((j0 + k) << 5));     // no dependency on deg

    float sx = 0.f, sy = 0.f;
#pragma unroll
    for (int k = 0; k < 8; k++) {
        if (j0 + k < deg) {
            float2 z = __ldg(zin + ids[k]);
            sx += z.x; sy += z.y;
        }
    }
    // rare continuation: deg > 16
    for (int j = j0 + 16; j < deg; j += 16) {
        int ids2[8];
#pragma unroll
        for (int k = 0; k < 8; k++)
            ids2[k] = __ldg(base + ((j + k) << 5));
#pragma unroll
        for (int k = 0; k < 8; k++) {
            if (j + k < deg) {
                float2 z = __ldg(zin + ids2[k]);
                sx += z.x; sy += z.y;
            }
        }
    }
    return make_float2(sx, sy);
}

// Fused pull + layer update: 2 threads per node, combined via shfl.
__global__ void k_layer(const float* __restrict__ W,  // [2][2][2]: W[p*4+in*2+out]
                        const float* __restrict__ b,  // [2][2]
                        int n, int inA) {
    int t = blockIdx.x * blockDim.x + threadIdx.x;
    int i = t >> 1;
    if (i >= n) return;
    int half = t & 1;
    const float2* zin = inA ? g_zpA : g_zpB;
    float2*      zout = inA ? g_zpB : g_zpA;

    const int* base = g_csr + (i >> 5) * (32 * SLOT) + (i & 31);
    int deg = min(g_cnt[i], SLOT);               // issued alongside first-batch ids
    float2 s = pull_half(zin, base, deg, half);

    unsigned mask = __activemask();              // pairs are both-active or both-exited
    s.x += __shfl_xor_sync(mask, s.x, 1);
    s.y += __shfl_xor_sync(mask, s.y, 1);
    if (half) return;

    float  dis = g_dis[i];
    float2 acc = g_acc[i];
    float x0 = fmaxf(acc.x + dis * s.x, 0.f);
    float x1 = fmaxf(acc.y + dis * s.y, 0.f);

    float a0 = x0 * W[0] + x1 * W[2] + b[0] + b[2];
    float a1 = x0 * W[1] + x1 * W[3] + b[1] + b[3];
    float z0 = x0 * W[4] + x1 * W[6];
    float z1 = x0 * W[5] + x1 * W[7];

    float d2 = dis * dis;
    zout[i]  = make_float2(z0 * dis, z1 * dis);
    g_acc[i] = make_float2(a0 + z0 * d2, a1 + z1 * d2);
}

__global__ void k_final(float2* __restrict__ out, int n, int inA) {
    int t = blockIdx.x * blockDim.x + threadIdx.x;
    int i = t >> 1;
    if (i >= n) return;
    int half = t & 1;
    const float2* zin = inA ? g_zpA : g_zpB;

    const int* base = g_csr + (i >> 5) * (32 * SLOT) + (i & 31);
    int deg = min(g_cnt[i], SLOT);
    float2 s = pull_half(zin, base, deg, half);

    unsigned mask = __activemask();
    s.x += __shfl_xor_sync(mask, s.x, 1);
    s.y += __shfl_xor_sync(mask, s.y, 1);
    if (half) return;

    float  dis = g_dis[i];
    float2 acc = g_acc[i];
    out[i] = make_float2(fmaxf(acc.x + dis * s.x, 0.f),
                         fmaxf(acc.y + dis * s.y, 0.f));
}

// ---------------------------------------------------------------------------
extern "C" void kernel_launch(void* const* d_in, const int* in_sizes, int n_in,
                              void* d_out, int out_size) {
    const float* X          = (const float*)d_in[0];
    const int*   edge_index = (const int*)  d_in[1];
    const int*   step_index = (const int*)  d_in[2];
    const float* step_emb   = (const float*)d_in[3];
    const float* W0         = (const float*)d_in[4];
    const float* b0         = (const float*)d_in[5];
    const float* Wh         = (const float*)d_in[6];
    const float* bh         = (const float*)d_in[7];

    int n = in_sizes[0] / 2;        // C = 2
    int e = in_sizes[1] / 2;        // edge_index is [2, E]
    const int* src = edge_index;
    const int* dst = edge_index + e;

    const int T = 256;
    int nb_node = (n + T - 1) / T;
    int nb_edge = ((e + 3) / 4 + T - 1) / T;
    int nb_pair = (2 * n + T - 1) / T;

    k_reset<<<nb_node, T>>>(n);
    k_fill<<<nb_edge, T>>>(src, dst, e);
    k_node0<<<nb_node, T>>>(X, step_index, step_emb, W0, b0, n);
    for (int l = 1; l <= 7; l++) {
        k_layer<<<nb_pair, T>>>(Wh + (l - 1) * 8, bh + (l - 1) * 4, n, l & 1);
    }
    k_final<<<nb_pair, T>>>((float2*)d_out, n, 0);
}